// round 15
// baseline (speedup 1.0000x reference)
#include <cuda_runtime.h>
#include <cstdint>

// ---------------------------------------------------------------------------
// ValueNetwork forward. Dead-code-eliminated: mlp1/global/attn branch unused.
// Live: self6 = state[:,0,:6]; LSTM(64 steps, in=7, hid=50); MLP 56->150->100->100->1.
// R15: == R14 dual-stream warps, with the REAL R13/R14 bug fixed: MLP layer-2
//      output (100x8=800 floats) overflowed XwA(448) into XwB, clobbering
//      stream B's input (bit-identical rel_err across sync changes proved a
//      deterministic overflow, not a race). New per-warp Zw scratch:
//      X->Y, Y->Z, Z->Y, out(Y) -- all disjoint.
// ---------------------------------------------------------------------------

#define B_SIZE 8192
#define NSTEP  64
#define ROWB   832          // floats per batch row of state (64*13)
#define HID    50
#define KDIM   57           // 7 input + 50 hidden
#define GATE   200
#define WSTR   256          // per-k weight stride (32 lanes * 8 slots, 7 used)
#define THREADS 128         // 4 warps
#define RPW    7            // rows per stream
#define RPB    56           // rows per block (4 warps * 2 streams * 7)
#define GRID   147          // ceil(8192/56)
// LSTM per-warp-stream regions
#define HX_FL   464                 // hx[58][8] (pad row; 16B-aligned stride)
#define GW_STR  9                   // gate col stride (odd -> conflict-free)
#define GW_FL   1808                // gates 200*9=1800, padded to 16B mult
#define WREG    4544                // per-warp: 2*HX + 2*GW

typedef unsigned long long ull;

// ---- f32x2 helpers --------------------------------------------------------
__device__ __forceinline__ ull dup2(float v) {
    ull r; asm("mov.b64 %0, {%1, %1};" : "=l"(r) : "f"(v)); return r;
}
__device__ __forceinline__ void fma2(ull& d, ull a, ull b) {
    asm("fma.rn.f32x2 %0, %1, %2, %0;" : "+l"(d) : "l"(a), "l"(b));
}
__device__ __forceinline__ float2 unpk(ull v) {
    float2 f; asm("mov.b64 {%0, %1}, %2;" : "=f"(f.x), "=f"(f.y) : "l"(v)); return f;
}
// ---- MUFU.TANH activations -------------------------------------------------
__device__ __forceinline__ float tanh_a(float x) {
    float y; asm("tanh.approx.f32 %0, %1;" : "=f"(y) : "f"(x)); return y;
}
__device__ __forceinline__ float sig_a(float x) {      // 0.5*tanh(x/2)+0.5
    return fmaf(tanh_a(0.5f * x), 0.5f, 0.5f);
}

// ---- smem layout ------------------------------------------------------------
// Phase A (LSTM): Wsh 57*256=14592 | 4 warps x (hxA 464 | hxB 464 | gwA 1808
//   | gwB 1808) -> ends 32768.
// Phase B (MLP) overwrites [0, 33868):
//   w1 8400 | b1 152 | w2 15000 | b2 104 | w3 10000 | b3 104 | w4 104 | b4 4+
// Per-warp X/Y/Z buffers at [33872, ...) in BOTH phases (disjoint from both).
#define OFF_W1 0
#define OFF_B1 8400
#define OFF_W2 8552
#define OFF_B2 23552
#define OFF_W3 23656
#define OFF_B3 33656
#define OFF_W4 33760
#define OFF_B4 33864
#define OFF_WB 33872
#define WB_FL  2896              // XA[56][8]=448 | XB 448 | Y[150][8]=1200 | Z[100][8]=800
#define SM_FLOATS (OFF_WB + 4 * WB_FL)
#define SM_BYTES  (SM_FLOATS * 4)

// MLP layer on warp-private buffers (stride-8 rows, 4 row-pairs incl pad)
template<int IN, int OUT, int LA, int CP>
__device__ __forceinline__ void mlp_layer8(const float* __restrict__ Wsh,
                                           const float* __restrict__ Bsh,
                                           const float* __restrict__ Xw,
                                           float* __restrict__ Yw, int lane)
{
    ull acc[4][CP];
    const bool act = lane < LA;
    #pragma unroll
    for (int j = 0; j < CP; ++j) {
        ull bv = dup2(act ? Bsh[j * LA + lane] : 0.f);
        acc[0][j] = bv; acc[1][j] = bv; acc[2][j] = bv; acc[3][j] = bv;
    }
    #pragma unroll 2
    for (int k = 0; k < IN; ++k) {
        const float* xr = Xw + k * 8;
        ull h0 = *(const ull*)(xr);
        ull h1 = *(const ull*)(xr + 2);
        ull h2 = *(const ull*)(xr + 4);
        ull h3 = *(const ull*)(xr + 6);
        #pragma unroll
        for (int j = 0; j < CP; ++j) {
            ull w2 = dup2(act ? Wsh[k * OUT + j * LA + lane] : 0.f);
            fma2(acc[0][j], h0, w2);
            fma2(acc[1][j], h1, w2);
            fma2(acc[2][j], h2, w2);
            fma2(acc[3][j], h3, w2);
        }
    }
    __syncwarp();       // all reads of Xw done before anyone writes Yw
    if (act) {
        #pragma unroll
        for (int j = 0; j < CP; ++j) {
            int c = j * LA + lane;
            float* yp = Yw + c * 8;
            #pragma unroll
            for (int rp = 0; rp < 4; ++rp) {
                float2 v = unpk(acc[rp][j]);
                v.x = fmaxf(v.x, 0.f);
                v.y = fmaxf(v.y, 0.f);
                *(float2*)(yp + 2 * rp) = v;
            }
        }
    }
    __syncwarp();
}

__global__ __launch_bounds__(THREADS, 1) void fused_kernel(
    const float* __restrict__ state,
    const float* __restrict__ wih, const float* __restrict__ whh,
    const float* __restrict__ bih, const float* __restrict__ bhh,
    const float* __restrict__ w1, const float* __restrict__ b1,
    const float* __restrict__ w2, const float* __restrict__ b2,
    const float* __restrict__ w3, const float* __restrict__ b3,
    const float* __restrict__ w4, const float* __restrict__ b4,
    float* __restrict__ out)
{
    extern __shared__ float sm[];
    float* Wsh = sm;                                    // 57*256

    const int tid  = threadIdx.x;
    const int lane = tid & 31;
    const int warp = tid >> 5;

    float* hxA = sm + KDIM * WSTR + warp * WREG;        // [58][8]
    float* hxB = hxA + HX_FL;
    float* gwA = hxB + HX_FL;                           // [200][9]
    float* gwB = gwA + GW_FL;

    const int b0A = blockIdx.x * RPB + warp * (2 * RPW);   // stream A rows
    const int b0B = b0A + RPW;                             // stream B rows

    // ======================= Phase A: LSTM =================================
    // weights: gate col 7*l+j at slot (k, 8*l+j); j==7 & c>=200 zero-padded
    for (int idx = tid; idx < KDIM * WSTR; idx += THREADS) {
        int k = idx >> 8, s = idx & 255, l = s >> 3, j = s & 7;
        int c = l * 7 + j;
        float v = 0.f;
        if (j < 7 && c < GATE)
            v = (k < 7) ? wih[k * GATE + c] : whh[(k - 7) * GATE + c];
        Wsh[idx] = v;
    }

    // scalar biases in registers (cols lane*7+j)
    float bflt[7];
    #pragma unroll
    for (int j = 0; j < 7; ++j) {
        int c = lane * 7 + j;
        bflt[j] = (c < GATE) ? bih[c] + bhh[c] : 0.f;
    }

    // zero hx (incl pad rows); c states in registers
    for (int i = lane; i < HX_FL; i += 32) { hxA[i] = 0.f; hxB[i] = 0.f; }
    float cregA[11], cregB[11];
    #pragma unroll
    for (int i = 0; i < 11; ++i) { cregA[i] = 0.f; cregB[i] = 0.f; }
    __syncwarp();   // zeros visible before x(0) stores to same region

    // x gather coords: 49 values (7 rows x 7 dims), clamped batch rows
    const int xr0 = lane / 7,        xk0 = lane - xr0 * 7;          // 0..31
    const int xr1 = (lane + 32) / 7, xk1 = (lane + 32) - xr1 * 7;   // 32..48
    const int i1ok = (lane + 32) < 49;
    const float* xp0A = state + (size_t)min(b0A + xr0, B_SIZE - 1) * ROWB + 6 + xk0;
    const float* xp1A = state + (size_t)min(b0A + (i1ok ? xr1 : 0), B_SIZE - 1) * ROWB + 6 + xk1;
    const float* xp0B = state + (size_t)min(b0B + xr0, B_SIZE - 1) * ROWB + 6 + xk0;
    const float* xp1B = state + (size_t)min(b0B + (i1ok ? xr1 : 0), B_SIZE - 1) * ROWB + 6 + xk1;

    // x(0)
    hxA[xk0 * 8 + xr0] = xp0A[0];
    if (i1ok) hxA[xk1 * 8 + xr1] = xp1A[0];
    hxB[xk0 * 8 + xr0] = xp0B[0];
    if (i1ok) hxB[xk1 * 8 + xr1] = xp1B[0];
    __syncthreads();    // Wsh + x(0) ready

    const float* wl = Wsh + (lane << 3);
    ull accA[3][7], accB[3][7];
    float accsA[7], accsB[7];

    // dual-stream GEMM body: weights + dups loaded ONCE for both streams;
    // h fetched as 2x LDS.128 per stream (row 6 = low half of p1.y)
    #define GEMM_K2(k)                                                    \
        {                                                                 \
            float4 wa = *(const float4*)(wl + ((k) << 8));                \
            float4 wb = *(const float4*)(wl + ((k) << 8) + 4);            \
            float w[7] = {wa.x, wa.y, wa.z, wa.w, wb.x, wb.y, wb.z};      \
            ulonglong2 pa0 = *(const ulonglong2*)(hxA + (k) * 8);         \
            ulonglong2 pa1 = *(const ulonglong2*)(hxA + (k) * 8 + 4);     \
            ulonglong2 pb0 = *(const ulonglong2*)(hxB + (k) * 8);         \
            ulonglong2 pb1 = *(const ulonglong2*)(hxB + (k) * 8 + 4);     \
            float a6 = unpk(pa1.y).x, b6 = unpk(pb1.y).x;                 \
            _Pragma("unroll")                                             \
            for (int j = 0; j < 7; ++j) {                                 \
                ull w2 = dup2(w[j]);                                      \
                fma2(accA[0][j], pa0.x, w2);                              \
                fma2(accA[1][j], pa0.y, w2);                              \
                fma2(accA[2][j], pa1.x, w2);                              \
                accsA[j] = fmaf(a6, w[j], accsA[j]);                      \
                fma2(accB[0][j], pb0.x, w2);                              \
                fma2(accB[1][j], pb0.y, w2);                              \
                fma2(accB[2][j], pb1.x, w2);                              \
                accsB[j] = fmaf(b6, w[j], accsB[j]);                      \
            }                                                             \
        }

    #define ACC_INIT()                                                    \
        _Pragma("unroll")                                                 \
        for (int j = 0; j < 7; ++j) {                                     \
            ull bv = dup2(bflt[j]);                                       \
            accA[0][j] = bv; accA[1][j] = bv; accA[2][j] = bv;            \
            accB[0][j] = bv; accB[1][j] = bv; accB[2][j] = bv;            \
            accsA[j] = bflt[j]; accsB[j] = bflt[j];                       \
        }

    // pre-loop: bias init + x-part for t=0
    ACC_INIT();
    #pragma unroll
    for (int k = 0; k < 7; ++k) GEMM_K2(k);

    for (int t = 0; t < NSTEP; ++t) {
        // prefetch x(t+1): LDG latency hidden under the h-part GEMM
        int t2 = (t < NSTEP - 1) ? t + 1 : t;
        float xv0A = xp0A[t2 * 13];
        float xv1A = i1ok ? xp1A[t2 * 13] : 0.f;
        float xv0B = xp0B[t2 * 13];
        float xv1B = i1ok ? xp1B[t2 * 13] : 0.f;

        // h-part GEMM: k = 7..56 (h(t), zero at t=0)
        #pragma unroll 5
        for (int k = 7; k < KDIM; ++k) GEMM_K2(k);

        // spill gates to warp-private smem (stride 9 -> conflict-free)
        #pragma unroll
        for (int j = 0; j < 7; ++j) {
            int c = lane * 7 + j;
            if (c < GATE) {
                float* gpA = gwA + c * GW_STR;
                float2 v;
                v = unpk(accA[0][j]); gpA[0] = v.x; gpA[1] = v.y;
                v = unpk(accA[1][j]); gpA[2] = v.x; gpA[3] = v.y;
                v = unpk(accA[2][j]); gpA[4] = v.x; gpA[5] = v.y;
                gpA[6] = accsA[j];
                float* gpB = gwB + c * GW_STR;
                v = unpk(accB[0][j]); gpB[0] = v.x; gpB[1] = v.y;
                v = unpk(accB[1][j]); gpB[2] = v.x; gpB[3] = v.y;
                v = unpk(accB[2][j]); gpB[4] = v.x; gpB[5] = v.y;
                gpB[6] = accsB[j];
            }
        }
        __syncwarp();   // gate stores & hx x-row reads done (cross-lane)

        // stage x(t+1) into hx rows 0..6
        hxA[xk0 * 8 + xr0] = xv0A;
        if (i1ok) hxA[xk1 * 8 + xr1] = xv1A;
        hxB[xk0 * 8 + xr0] = xv0B;
        if (i1ok) hxB[xk1 * 8 + xr1] = xv1B;
        __syncwarp();   // x visible to all lanes' x-part reads

        // --- x-part GEMM(t+1) [FMA] + activation(t) [MUFU] overlap ---
        ACC_INIT();
        #pragma unroll
        for (int k = 0; k < 7; ++k) GEMM_K2(k);

        // activation: 50 units x 7 rows per stream, c in regs (MUFU.TANH)
        #pragma unroll
        for (int i = 0; i < 11; ++i) {
            int idx = lane + 32 * i;
            if (idx < HID * RPW) {
                int u = idx / 7, rr = idx - u * 7;
                float gi = gwA[u * GW_STR + rr];
                float gf = gwA[(HID + u) * GW_STR + rr];
                float gg = gwA[(2 * HID + u) * GW_STR + rr];
                float go = gwA[(3 * HID + u) * GW_STR + rr];
                float c = sig_a(gf) * cregA[i] + sig_a(gi) * tanh_a(gg);
                cregA[i] = c;
                hxA[(7 + u) * 8 + rr] = sig_a(go) * tanh_a(c);
            }
        }
        #pragma unroll
        for (int i = 0; i < 11; ++i) {
            int idx = lane + 32 * i;
            if (idx < HID * RPW) {
                int u = idx / 7, rr = idx - u * 7;
                float gi = gwB[u * GW_STR + rr];
                float gf = gwB[(HID + u) * GW_STR + rr];
                float gg = gwB[(2 * HID + u) * GW_STR + rr];
                float go = gwB[(3 * HID + u) * GW_STR + rr];
                float c = sig_a(gf) * cregB[i] + sig_a(gi) * tanh_a(gg);
                cregB[i] = c;
                hxB[(7 + u) * 8 + rr] = sig_a(go) * tanh_a(c);
            }
        }
        __syncwarp();   // h visible before next h-part GEMM (cross-lane)
    }
    #undef GEMM_K2
    #undef ACC_INIT

    // ================== Phase A->B transition ==============================
    float* XwA = sm + OFF_WB + warp * WB_FL;            // [56][8]
    float* XwB = XwA + 448;                             // [56][8]
    float* Yw  = XwB + 448;                             // [150][8] shared
    float* Zw  = Yw + 1200;                             // [100][8] scratch

    for (int i = lane; i < 896; i += 32) XwA[i] = 0.f;  // zero XA+XB
    __syncwarp();   // zeros ordered before cross-lane h/self6 writes below
    // h rows from hx (still intact)
    #pragma unroll
    for (int i = 0; i < 11; ++i) {
        int idx = lane + 32 * i;
        if (idx < HID * RPW) {
            int u = idx / 7, rr = idx - u * 7;
            XwA[(6 + u) * 8 + rr] = hxA[(7 + u) * 8 + rr];
            XwB[(6 + u) * 8 + rr] = hxB[(7 + u) * 8 + rr];
        }
    }
    // self6: 42 values (7 rows x 6 dims) per stream, clamped rows
    {
        int idx0 = lane;
        int r0 = idx0 / 6, k0 = idx0 - r0 * 6;
        int idx1 = lane + 32;
        int r1 = idx1 / 6, k1 = idx1 - r1 * 6;
        if (idx0 < 42) {
            XwA[k0 * 8 + r0] = state[(size_t)min(b0A + r0, B_SIZE - 1) * ROWB + k0];
            XwB[k0 * 8 + r0] = state[(size_t)min(b0B + r0, B_SIZE - 1) * ROWB + k0];
        }
        if (idx1 < 42) {
            XwA[k1 * 8 + r1] = state[(size_t)min(b0A + r1, B_SIZE - 1) * ROWB + k1];
            XwB[k1 * 8 + r1] = state[(size_t)min(b0B + r1, B_SIZE - 1) * ROWB + k1];
        }
    }
    __syncthreads();    // everyone done with LSTM smem

    // stage MLP weights over the dead LSTM region
    float* w1s = sm + OFF_W1;
    float* b1s = sm + OFF_B1;
    float* w2s = sm + OFF_W2;
    float* b2s = sm + OFF_B2;
    float* w3s = sm + OFF_W3;
    float* b3s = sm + OFF_B3;
    float* w4s = sm + OFF_W4;
    float* b4s = sm + OFF_B4;
    for (int i = tid; i < 2100; i += THREADS)
        ((float4*)w1s)[i] = ((const float4*)w1)[i];
    for (int i = tid; i < 3750; i += THREADS)
        ((float4*)w2s)[i] = ((const float4*)w2)[i];
    for (int i = tid; i < 2500; i += THREADS)
        ((float4*)w3s)[i] = ((const float4*)w3)[i];
    if (tid < 100) {
        b1s[tid] = b1[tid]; b1s[tid + 50] = b1[tid + 50];
        b2s[tid] = b2[tid]; b3s[tid] = b3[tid]; w4s[tid] = w4[tid];
    }
    if (tid == 0) b4s[0] = b4[0];
    __syncthreads();    // weights visible

    // ======================= Phase B: MLP (per stream) =====================
    // Buffer chain X->Y->Z->Y: every layer's input and output are disjoint.
    #pragma unroll 1
    for (int s = 0; s < 2; ++s) {
        float* Xw = s ? XwB : XwA;
        const int b0 = s ? b0B : b0A;

        mlp_layer8<56, 150, 30, 5>(w1s, b1s, Xw, Yw, lane);
        mlp_layer8<150, 100, 25, 4>(w2s, b2s, Yw, Zw, lane);
        mlp_layer8<100, 100, 25, 4>(w3s, b3s, Zw, Yw, lane);

        // output: 8 rows (7 real), 4 lanes per row, shfl reduce
        int r  = lane >> 2;          // 0..7
        int kk = lane & 3;           // 0..3
        float a = 0.f;
        #pragma unroll 5
        for (int k = kk; k < 100; k += 4)
            a = fmaf(Yw[k * 8 + r], w4s[k], a);
        a += __shfl_down_sync(0xFFFFFFFF, a, 2);
        a += __shfl_down_sync(0xFFFFFFFF, a, 1);
        if (kk == 0 && r < RPW && b0 + r < B_SIZE)
            out[b0 + r] = a + b4s[0];
        __syncwarp();   // Yw reads done before next stream overwrites it
    }
}

// ---------------------------------------------------------------------------
extern "C" void kernel_launch(void* const* d_in, const int* in_sizes, int n_in,
                              void* d_out, int out_size)
{
    (void)in_sizes; (void)n_in; (void)out_size;
    const float* state = (const float*)d_in[0];
    const float* wih   = (const float*)d_in[11];
    const float* whh   = (const float*)d_in[12];
    const float* bih   = (const float*)d_in[13];
    const float* bhh   = (const float*)d_in[14];
    const float* w1    = (const float*)d_in[15];
    const float* b1    = (const float*)d_in[16];
    const float* w2    = (const float*)d_in[17];
    const float* b2    = (const float*)d_in[18];
    const float* w3    = (const float*)d_in[19];
    const float* b3    = (const float*)d_in[20];
    const float* w4    = (const float*)d_in[21];
    const float* b4    = (const float*)d_in[22];
    float* out = (float*)d_out;

    cudaFuncSetAttribute(fused_kernel, cudaFuncAttributeMaxDynamicSharedMemorySize, SM_BYTES);

    fused_kernel<<<GRID, THREADS, SM_BYTES>>>(state, wih, whh, bih, bhh,
                                              w1, b1, w2, b2, w3, b3, w4, b4,
                                              out);
}

// round 16
// speedup vs baseline: 1.1024x; 1.1024x over previous
#include <cuda_runtime.h>
#include <cstdint>

// ---------------------------------------------------------------------------
// ValueNetwork forward. Dead-code-eliminated: mlp1/global/attn branch unused.
// Live: self6 = state[:,0,:6]; LSTM(64 steps, in=7, hid=50); MLP 56->150->100->100->1.
// R16: revert to R12 (dual-stream dead: R15 regs=255 spills, occ 6.3%).
//      Single change vs R12: the x-part GEMM(t+1) and activation(t) are
//      MANUALLY INTERLEAVED (k0,a0,a1,k1,a2,...) so FMA-pipe and MUFU-pipe
//      work alternates in program order -- ptxas can't hoist across the big
//      activation block at 212 regs, so we do it in source.
// ---------------------------------------------------------------------------

#define B_SIZE 8192
#define NSTEP  64
#define ROWB   832          // floats per batch row of state (64*13)
#define HID    50
#define KDIM   57           // 7 input + 50 hidden
#define GATE   200
#define WSTR   256          // per-k weight stride (32 lanes * 8 slots, 7 used)
#define THREADS 256
#define RPW    7            // batch rows per warp
#define RPB    56           // rows per block (8 warps * 7)
#define GRID   147          // ceil(8192/56)
// LSTM per-warp regions
#define HXW_FL  (KDIM * 8)          // 456: hx[k][8 slots] (slot 7 unused)
#define GW_STR  9                   // gate col stride (odd -> conflict-free)
#define GW_FL   (GATE * GW_STR)     // 1800

typedef unsigned long long ull;

// ---- f32x2 helpers --------------------------------------------------------
__device__ __forceinline__ ull dup2(float v) {
    ull r; asm("mov.b64 %0, {%1, %1};" : "=l"(r) : "f"(v)); return r;
}
__device__ __forceinline__ void fma2(ull& d, ull a, ull b) {
    asm("fma.rn.f32x2 %0, %1, %2, %0;" : "+l"(d) : "l"(a), "l"(b));
}
__device__ __forceinline__ float2 unpk(ull v) {
    float2 f; asm("mov.b64 {%0, %1}, %2;" : "=f"(f.x), "=f"(f.y) : "l"(v)); return f;
}
// ---- MUFU.TANH activations -------------------------------------------------
__device__ __forceinline__ float tanh_a(float x) {
    float y; asm("tanh.approx.f32 %0, %1;" : "=f"(y) : "f"(x)); return y;
}
__device__ __forceinline__ float sig_a(float x) {      // 0.5*tanh(x/2)+0.5
    return fmaf(tanh_a(0.5f * x), 0.5f, 0.5f);
}

// ---- smem layout ------------------------------------------------------------
// Phase A (LSTM): [0, 32640) floats:
//   Wsh 57*256 | per-warp hx[57][8] | per-warp gates[200][9]
// Phase B (MLP) overwrites [0, 33866):
//   w1 8400 | b1 152 | w2 15000 | b2 104 | w3 10000 | b3 104 | w4 104 | b4 4
// Per-warp X/Y buffers live at [33868, 47052) in BOTH phases (disjoint).
#define OFF_W1 0
#define OFF_B1 8400
#define OFF_W2 8552
#define OFF_B2 23552
#define OFF_W3 23656
#define OFF_B3 33656
#define OFF_W4 33760
#define OFF_B4 33864
#define OFF_WB 33868
#define WB_FL  1648              // per-warp: X[56][8]=448 | Y[150][8]=1200
#define SM_FLOATS (OFF_WB + 8 * WB_FL)
#define SM_BYTES  (SM_FLOATS * 4)

// MLP layer on warp-private buffers (stride-8 rows, 4 row-pairs incl pad row 7)
template<int IN, int OUT, int LA, int CP>
__device__ __forceinline__ void mlp_layer8(const float* __restrict__ Wsh,
                                           const float* __restrict__ Bsh,
                                           const float* __restrict__ Xw,
                                           float* __restrict__ Yw, int lane)
{
    ull acc[4][CP];
    const bool act = lane < LA;
    #pragma unroll
    for (int j = 0; j < CP; ++j) {
        ull bv = dup2(act ? Bsh[j * LA + lane] : 0.f);
        acc[0][j] = bv; acc[1][j] = bv; acc[2][j] = bv; acc[3][j] = bv;
    }
    #pragma unroll 2
    for (int k = 0; k < IN; ++k) {
        const float* xr = Xw + k * 8;
        ull h0 = *(const ull*)(xr);
        ull h1 = *(const ull*)(xr + 2);
        ull h2 = *(const ull*)(xr + 4);
        ull h3 = *(const ull*)(xr + 6);
        #pragma unroll
        for (int j = 0; j < CP; ++j) {
            ull w2 = dup2(act ? Wsh[k * OUT + j * LA + lane] : 0.f);
            fma2(acc[0][j], h0, w2);
            fma2(acc[1][j], h1, w2);
            fma2(acc[2][j], h2, w2);
            fma2(acc[3][j], h3, w2);
        }
    }
    if (act) {
        #pragma unroll
        for (int j = 0; j < CP; ++j) {
            int c = j * LA + lane;
            float* yp = Yw + c * 8;
            #pragma unroll
            for (int rp = 0; rp < 4; ++rp) {
                float2 v = unpk(acc[rp][j]);
                v.x = fmaxf(v.x, 0.f);
                v.y = fmaxf(v.y, 0.f);
                *(float2*)(yp + 2 * rp) = v;
            }
        }
    }
    __syncwarp();
}

__global__ __launch_bounds__(THREADS, 1) void fused_kernel(
    const float* __restrict__ state,
    const float* __restrict__ wih, const float* __restrict__ whh,
    const float* __restrict__ bih, const float* __restrict__ bhh,
    const float* __restrict__ w1, const float* __restrict__ b1,
    const float* __restrict__ w2, const float* __restrict__ b2,
    const float* __restrict__ w3, const float* __restrict__ b3,
    const float* __restrict__ w4, const float* __restrict__ b4,
    float* __restrict__ out)
{
    extern __shared__ float sm[];
    float* Wsh = sm;                                    // 57*256

    const int tid  = threadIdx.x;
    const int lane = tid & 31;
    const int warp = tid >> 5;

    float* hxw = sm + KDIM * WSTR + warp * HXW_FL;      // [k][8]
    float* gw  = sm + KDIM * WSTR + 8 * HXW_FL + warp * GW_FL;  // [c][9]
    float* Xw  = sm + OFF_WB + warp * WB_FL;            // [56][8]
    float* Yw  = Xw + 448;                              // [150][8]

    const int b0 = blockIdx.x * RPB + warp * RPW;       // warp's 7 rows

    // ======================= Phase A: LSTM =================================
    // weights: gate col 7*l+j at slot (k, 8*l+j); j==7 & c>=200 zero-padded
    for (int idx = tid; idx < KDIM * WSTR; idx += THREADS) {
        int k = idx >> 8, s = idx & 255, l = s >> 3, j = s & 7;
        int c = l * 7 + j;
        float v = 0.f;
        if (j < 7 && c < GATE)
            v = (k < 7) ? wih[k * GATE + c] : whh[(k - 7) * GATE + c];
        Wsh[idx] = v;
    }

    // biases into registers (cols lane*7+j), dup + scalar forms
    ull bdup[7]; float bflt[7];
    #pragma unroll
    for (int j = 0; j < 7; ++j) {
        int c = lane * 7 + j;
        bflt[j] = (c < GATE) ? bih[c] + bhh[c] : 0.f;
        bdup[j] = dup2(bflt[j]);
    }

    // zero hx; c state lives in registers (7 rows * 50 units / 32 lanes -> 11)
    for (int i = lane; i < HXW_FL; i += 32) hxw[i] = 0.f;
    float creg[11];
    #pragma unroll
    for (int i = 0; i < 11; ++i) creg[i] = 0.f;

    // x gather coords: 49 values (7 rows x 7 dims), clamped batch rows
    const int xr0 = lane / 7,        xk0 = lane - xr0 * 7;          // idx 0..31
    const int xr1 = (lane + 32) / 7, xk1 = (lane + 32) - xr1 * 7;   // idx 32..48
    const int i1ok = (lane + 32) < 49;
    const int bR0 = min(b0 + xr0, B_SIZE - 1);
    const int bR1 = min(b0 + (i1ok ? xr1 : 0), B_SIZE - 1);
    const float* xp0 = state + (size_t)bR0 * ROWB + 6 + xk0;
    const float* xp1 = state + (size_t)bR1 * ROWB + 6 + xk1;

    // x(0)
    hxw[xk0 * 8 + xr0] = xp0[0];
    if (i1ok) hxw[xk1 * 8 + xr1] = xp1[0];
    __syncthreads();    // Wsh ready

    const float* wl = Wsh + (lane << 3);
    ull acc[3][7]; float accs[7];

    // 7-row GEMM body: rows (0,1),(2,3),(4,5) paired + row 6 scalar
    #define GEMM_K7(k)                                                    \
        {                                                                 \
            const float* hb = hxw + (k) * 8;                              \
            ull h0 = *(const ull*)(hb);                                   \
            ull h1 = *(const ull*)(hb + 2);                               \
            ull h2 = *(const ull*)(hb + 4);                               \
            float h6 = hb[6];                                             \
            float4 wa = *(const float4*)(wl + ((k) << 8));                \
            float4 wb = *(const float4*)(wl + ((k) << 8) + 4);            \
            float w[7] = {wa.x, wa.y, wa.z, wa.w, wb.x, wb.y, wb.z};      \
            _Pragma("unroll")                                             \
            for (int j = 0; j < 7; ++j) {                                 \
                ull w2 = dup2(w[j]);                                      \
                fma2(acc[0][j], h0, w2);                                  \
                fma2(acc[1][j], h1, w2);                                  \
                fma2(acc[2][j], h2, w2);                                  \
                accs[j] = fmaf(h6, w[j], accs[j]);                        \
            }                                                             \
        }

    // one activation iteration (unit-block i): 4 LDS + 5 MUFU + FMAs + STS
    #define ACT_I(i)                                                      \
        {                                                                 \
            int idx = lane + 32 * (i);                                    \
            if (idx < HID * RPW) {                                        \
                int u = idx / 7, rr = idx - u * 7;                        \
                float gi = gw[u * GW_STR + rr];                           \
                float gf = gw[(HID + u) * GW_STR + rr];                   \
                float gg = gw[(2 * HID + u) * GW_STR + rr];               \
                float go = gw[(3 * HID + u) * GW_STR + rr];               \
                float c = sig_a(gf) * creg[i] + sig_a(gi) * tanh_a(gg);   \
                creg[i] = c;                                              \
                hxw[(7 + u) * 8 + rr] = sig_a(go) * tanh_a(c);            \
            }                                                             \
        }

    // pre-loop: bias init + x-part for t=0
    #pragma unroll
    for (int j = 0; j < 7; ++j) {
        acc[0][j] = bdup[j]; acc[1][j] = bdup[j]; acc[2][j] = bdup[j];
        accs[j] = bflt[j];
    }
    #pragma unroll
    for (int k = 0; k < 7; ++k) GEMM_K7(k);

    for (int t = 0; t < NSTEP; ++t) {
        // prefetch x(t+1)
        int t2 = (t < NSTEP - 1) ? t + 1 : t;
        float xv0 = xp0[t2 * 13];
        float xv1 = i1ok ? xp1[t2 * 13] : 0.f;

        // h-part GEMM: k = 7..56
        #pragma unroll 5
        for (int k = 7; k < KDIM; ++k) GEMM_K7(k);

        // spill gates (float stores, stride 9 -> conflict-free)
        #pragma unroll
        for (int j = 0; j < 7; ++j) {
            int c = lane * 7 + j;
            if (c < GATE) {
                float* gp = gw + c * GW_STR;
                float2 v0 = unpk(acc[0][j]); gp[0] = v0.x; gp[1] = v0.y;
                float2 v1 = unpk(acc[1][j]); gp[2] = v1.x; gp[3] = v1.y;
                float2 v2 = unpk(acc[2][j]); gp[4] = v2.x; gp[5] = v2.y;
                gp[6] = accs[j];
            }
        }
        __syncwarp();   // gate stores & hx row reads done

        // stage x(t+1)
        hxw[xk0 * 8 + xr0] = xv0;
        if (i1ok) hxw[xk1 * 8 + xr1] = xv1;
        __syncwarp();

        // --- MANUALLY INTERLEAVED: x-part GEMM(t+1) [FMA pipe] woven with
        //     activation(t) [MUFU pipe]. x-part reads hx rows 0-6 only;
        //     activation writes rows 7-56 only -> independent. ---
        #pragma unroll
        for (int j = 0; j < 7; ++j) {
            acc[0][j] = bdup[j]; acc[1][j] = bdup[j]; acc[2][j] = bdup[j];
            accs[j] = bflt[j];
        }
        GEMM_K7(0); ACT_I(0);  ACT_I(1);
        GEMM_K7(1); ACT_I(2);
        GEMM_K7(2); ACT_I(3);  ACT_I(4);
        GEMM_K7(3); ACT_I(5);
        GEMM_K7(4); ACT_I(6);  ACT_I(7);
        GEMM_K7(5); ACT_I(8);
        GEMM_K7(6); ACT_I(9);  ACT_I(10);

        __syncwarp();   // h visible before next h-part GEMM
    }
    #undef GEMM_K7
    #undef ACT_I

    // ================== Phase A->B transition ==============================
    // Build warp-private X = [self6 | h] (rows 0..6, pad row 7) in the
    // disjoint Xw region; zero first.
    for (int i = lane; i < 448; i += 32) Xw[i] = 0.f;
    __syncwarp();
    // h rows from hxw (still intact)
    #pragma unroll
    for (int i = 0; i < 11; ++i) {
        int idx = lane + 32 * i;
        if (idx < HID * RPW) {
            int u = idx / 7, rr = idx - u * 7;
            Xw[(6 + u) * 8 + rr] = hxw[(7 + u) * 8 + rr];
        }
    }
    // self6: 42 values (7 rows x 6 dims), clamped rows
    {
        int idx0 = lane;                 // < 42 for all lanes 0..31
        int r0 = idx0 / 6, k0 = idx0 - r0 * 6;
        if (idx0 < 42)
            Xw[k0 * 8 + r0] = state[(size_t)min(b0 + r0, B_SIZE - 1) * ROWB + k0];
        int idx1 = lane + 32;
        int r1 = idx1 / 6, k1 = idx1 - r1 * 6;
        if (idx1 < 42)
            Xw[k1 * 8 + r1] = state[(size_t)min(b0 + r1, B_SIZE - 1) * ROWB + k1];
    }
    __syncthreads();    // everyone done with LSTM smem

    // stage MLP weights over the dead LSTM region
    float* w1s = sm + OFF_W1;
    float* b1s = sm + OFF_B1;
    float* w2s = sm + OFF_W2;
    float* b2s = sm + OFF_B2;
    float* w3s = sm + OFF_W3;
    float* b3s = sm + OFF_B3;
    float* w4s = sm + OFF_W4;
    float* b4s = sm + OFF_B4;
    for (int i = tid; i < 2100; i += THREADS)
        ((float4*)w1s)[i] = ((const float4*)w1)[i];
    for (int i = tid; i < 3750; i += THREADS)
        ((float4*)w2s)[i] = ((const float4*)w2)[i];
    for (int i = tid; i < 2500; i += THREADS)
        ((float4*)w3s)[i] = ((const float4*)w3)[i];
    if (tid < 150) b1s[tid] = b1[tid];
    if (tid < 100) { b2s[tid] = b2[tid]; b3s[tid] = b3[tid]; w4s[tid] = w4[tid]; }
    if (tid == 0) b4s[0] = b4[0];
    __syncthreads();    // weights visible

    // ======================= Phase B: MLP ==================================
    mlp_layer8<56, 150, 30, 5>(w1s, b1s, Xw, Yw, lane);
    mlp_layer8<150, 100, 25, 4>(w2s, b2s, Yw, Xw, lane);
    mlp_layer8<100, 100, 25, 4>(w3s, b3s, Xw, Yw, lane);

    // output: 8 rows (7 real), 4 lanes per row, shfl reduce
    {
        int r  = lane >> 2;          // 0..7
        int kk = lane & 3;           // 0..3
        float a = 0.f;
        #pragma unroll 5
        for (int k = kk; k < 100; k += 4)
            a = fmaf(Yw[k * 8 + r], w4s[k], a);
        a += __shfl_down_sync(0xFFFFFFFF, a, 2);
        a += __shfl_down_sync(0xFFFFFFFF, a, 1);
        if (kk == 0 && r < RPW && b0 + r < B_SIZE)
            out[b0 + r] = a + b4s[0];
    }
}

// ---------------------------------------------------------------------------
extern "C" void kernel_launch(void* const* d_in, const int* in_sizes, int n_in,
                              void* d_out, int out_size)
{
    (void)in_sizes; (void)n_in; (void)out_size;
    const float* state = (const float*)d_in[0];
    const float* wih   = (const float*)d_in[11];
    const float* whh   = (const float*)d_in[12];
    const float* bih   = (const float*)d_in[13];
    const float* bhh   = (const float*)d_in[14];
    const float* w1    = (const float*)d_in[15];
    const float* b1    = (const float*)d_in[16];
    const float* w2    = (const float*)d_in[17];
    const float* b2    = (const float*)d_in[18];
    const float* w3    = (const float*)d_in[19];
    const float* b3    = (const float*)d_in[20];
    const float* w4    = (const float*)d_in[21];
    const float* b4    = (const float*)d_in[22];
    float* out = (float*)d_out;

    cudaFuncSetAttribute(fused_kernel, cudaFuncAttributeMaxDynamicSharedMemorySize, SM_BYTES);

    fused_kernel<<<GRID, THREADS, SM_BYTES>>>(state, wih, whh, bih, bhh,
                                              w1, b1, w2, b2, w3, b3, w4, b4,
                                              out);
}

// round 17
// speedup vs baseline: 1.1039x; 1.0014x over previous
#include <cuda_runtime.h>
#include <cstdint>

// ---------------------------------------------------------------------------
// ValueNetwork forward. Dead-code-eliminated: mlp1/global/attn branch unused.
// Live: self6 = state[:,0,:6]; LSTM(64 steps, in=7, hid=50); MLP 56->150->100->100->1.
// R17: == R16 (interleaved x-part/activation) + h-loads vectorized:
//      3xLDS.64+1xLDS.32 (4 broadcast wavefronts) -> 2xLDS.128 (2 wf).
//      Kernel is crossbar-bound (L1 84.1%); this cuts ~15% of the binding
//      resource. hx slot 7 is permanently zero -> safe to read as pad.
// ---------------------------------------------------------------------------

#define B_SIZE 8192
#define NSTEP  64
#define ROWB   832          // floats per batch row of state (64*13)
#define HID    50
#define KDIM   57           // 7 input + 50 hidden
#define GATE   200
#define WSTR   256          // per-k weight stride (32 lanes * 8 slots, 7 used)
#define THREADS 256
#define RPW    7            // batch rows per warp
#define RPB    56           // rows per block (8 warps * 7)
#define GRID   147          // ceil(8192/56)
// LSTM per-warp regions
#define HXW_FL  (KDIM * 8)          // 456: hx[k][8 slots] (slot 7 = zero pad)
#define GW_STR  9                   // gate col stride (odd -> conflict-free)
#define GW_FL   (GATE * GW_STR)     // 1800

typedef unsigned long long ull;

// ---- f32x2 helpers --------------------------------------------------------
__device__ __forceinline__ ull dup2(float v) {
    ull r; asm("mov.b64 %0, {%1, %1};" : "=l"(r) : "f"(v)); return r;
}
__device__ __forceinline__ void fma2(ull& d, ull a, ull b) {
    asm("fma.rn.f32x2 %0, %1, %2, %0;" : "+l"(d) : "l"(a), "l"(b));
}
__device__ __forceinline__ float2 unpk(ull v) {
    float2 f; asm("mov.b64 {%0, %1}, %2;" : "=f"(f.x), "=f"(f.y) : "l"(v)); return f;
}
// ---- MUFU.TANH activations -------------------------------------------------
__device__ __forceinline__ float tanh_a(float x) {
    float y; asm("tanh.approx.f32 %0, %1;" : "=f"(y) : "f"(x)); return y;
}
__device__ __forceinline__ float sig_a(float x) {      // 0.5*tanh(x/2)+0.5
    return fmaf(tanh_a(0.5f * x), 0.5f, 0.5f);
}

// ---- smem layout ------------------------------------------------------------
// Phase A (LSTM): [0, 32640) floats:
//   Wsh 57*256 | per-warp hx[57][8] | per-warp gates[200][9]
// Phase B (MLP) overwrites [0, 33866):
//   w1 8400 | b1 152 | w2 15000 | b2 104 | w3 10000 | b3 104 | w4 104 | b4 4
// Per-warp X/Y buffers live at [33868, 47052) in BOTH phases (disjoint).
#define OFF_W1 0
#define OFF_B1 8400
#define OFF_W2 8552
#define OFF_B2 23552
#define OFF_W3 23656
#define OFF_B3 33656
#define OFF_W4 33760
#define OFF_B4 33864
#define OFF_WB 33868
#define WB_FL  1648              // per-warp: X[56][8]=448 | Y[150][8]=1200
#define SM_FLOATS (OFF_WB + 8 * WB_FL)
#define SM_BYTES  (SM_FLOATS * 4)

// MLP layer on warp-private buffers (stride-8 rows, 4 row-pairs incl pad row 7)
template<int IN, int OUT, int LA, int CP>
__device__ __forceinline__ void mlp_layer8(const float* __restrict__ Wsh,
                                           const float* __restrict__ Bsh,
                                           const float* __restrict__ Xw,
                                           float* __restrict__ Yw, int lane)
{
    ull acc[4][CP];
    const bool act = lane < LA;
    #pragma unroll
    for (int j = 0; j < CP; ++j) {
        ull bv = dup2(act ? Bsh[j * LA + lane] : 0.f);
        acc[0][j] = bv; acc[1][j] = bv; acc[2][j] = bv; acc[3][j] = bv;
    }
    #pragma unroll 2
    for (int k = 0; k < IN; ++k) {
        const float* xr = Xw + k * 8;
        ulonglong2 xp0 = *(const ulonglong2*)(xr);      // rows 0-3
        ulonglong2 xp1 = *(const ulonglong2*)(xr + 4);  // rows 4-7
        #pragma unroll
        for (int j = 0; j < CP; ++j) {
            ull w2 = dup2(act ? Wsh[k * OUT + j * LA + lane] : 0.f);
            fma2(acc[0][j], xp0.x, w2);
            fma2(acc[1][j], xp0.y, w2);
            fma2(acc[2][j], xp1.x, w2);
            fma2(acc[3][j], xp1.y, w2);
        }
    }
    if (act) {
        #pragma unroll
        for (int j = 0; j < CP; ++j) {
            int c = j * LA + lane;
            float* yp = Yw + c * 8;
            #pragma unroll
            for (int rp = 0; rp < 4; ++rp) {
                float2 v = unpk(rp == 0 ? acc[0][j] : rp == 1 ? acc[1][j]
                                : rp == 2 ? acc[2][j] : acc[3][j]);
                v.x = fmaxf(v.x, 0.f);
                v.y = fmaxf(v.y, 0.f);
                *(float2*)(yp + 2 * rp) = v;
            }
        }
    }
    __syncwarp();
}

__global__ __launch_bounds__(THREADS, 1) void fused_kernel(
    const float* __restrict__ state,
    const float* __restrict__ wih, const float* __restrict__ whh,
    const float* __restrict__ bih, const float* __restrict__ bhh,
    const float* __restrict__ w1, const float* __restrict__ b1,
    const float* __restrict__ w2, const float* __restrict__ b2,
    const float* __restrict__ w3, const float* __restrict__ b3,
    const float* __restrict__ w4, const float* __restrict__ b4,
    float* __restrict__ out)
{
    extern __shared__ float sm[];
    float* Wsh = sm;                                    // 57*256

    const int tid  = threadIdx.x;
    const int lane = tid & 31;
    const int warp = tid >> 5;

    float* hxw = sm + KDIM * WSTR + warp * HXW_FL;      // [k][8]
    float* gw  = sm + KDIM * WSTR + 8 * HXW_FL + warp * GW_FL;  // [c][9]
    float* Xw  = sm + OFF_WB + warp * WB_FL;            // [56][8]
    float* Yw  = Xw + 448;                              // [150][8]

    const int b0 = blockIdx.x * RPB + warp * RPW;       // warp's 7 rows

    // ======================= Phase A: LSTM =================================
    // weights: gate col 7*l+j at slot (k, 8*l+j); j==7 & c>=200 zero-padded
    for (int idx = tid; idx < KDIM * WSTR; idx += THREADS) {
        int k = idx >> 8, s = idx & 255, l = s >> 3, j = s & 7;
        int c = l * 7 + j;
        float v = 0.f;
        if (j < 7 && c < GATE)
            v = (k < 7) ? wih[k * GATE + c] : whh[(k - 7) * GATE + c];
        Wsh[idx] = v;
    }

    // biases into registers (cols lane*7+j), dup + scalar forms
    ull bdup[7]; float bflt[7];
    #pragma unroll
    for (int j = 0; j < 7; ++j) {
        int c = lane * 7 + j;
        bflt[j] = (c < GATE) ? bih[c] + bhh[c] : 0.f;
        bdup[j] = dup2(bflt[j]);
    }

    // zero hx (slot 7 of every row stays zero forever -> LDS.128 pad safe);
    // c state lives in registers (7 rows * 50 units / 32 lanes -> 11)
    for (int i = lane; i < HXW_FL; i += 32) hxw[i] = 0.f;
    float creg[11];
    #pragma unroll
    for (int i = 0; i < 11; ++i) creg[i] = 0.f;

    // x gather coords: 49 values (7 rows x 7 dims), clamped batch rows
    const int xr0 = lane / 7,        xk0 = lane - xr0 * 7;          // idx 0..31
    const int xr1 = (lane + 32) / 7, xk1 = (lane + 32) - xr1 * 7;   // idx 32..48
    const int i1ok = (lane + 32) < 49;
    const int bR0 = min(b0 + xr0, B_SIZE - 1);
    const int bR1 = min(b0 + (i1ok ? xr1 : 0), B_SIZE - 1);
    const float* xp0 = state + (size_t)bR0 * ROWB + 6 + xk0;
    const float* xp1 = state + (size_t)bR1 * ROWB + 6 + xk1;

    // x(0)
    hxw[xk0 * 8 + xr0] = xp0[0];
    if (i1ok) hxw[xk1 * 8 + xr1] = xp1[0];
    __syncthreads();    // Wsh ready

    const float* wl = Wsh + (lane << 3);
    ull acc[3][7]; float accs[7];

    // 7-row GEMM body: rows (0,1),(2,3),(4,5) paired + row 6 scalar.
    // h fetched as 2x LDS.128 broadcast (2 wavefronts, was 4).
    #define GEMM_K7(k)                                                    \
        {                                                                 \
            const float* hb = hxw + (k) * 8;                              \
            ulonglong2 hp0 = *(const ulonglong2*)(hb);                    \
            ulonglong2 hp1 = *(const ulonglong2*)(hb + 4);                \
            ull h0 = hp0.x, h1 = hp0.y, h2 = hp1.x;                       \
            float h6 = unpk(hp1.y).x;                                     \
            float4 wa = *(const float4*)(wl + ((k) << 8));                \
            float4 wb = *(const float4*)(wl + ((k) << 8) + 4);            \
            float w[7] = {wa.x, wa.y, wa.z, wa.w, wb.x, wb.y, wb.z};      \
            _Pragma("unroll")                                             \
            for (int j = 0; j < 7; ++j) {                                 \
                ull w2 = dup2(w[j]);                                      \
                fma2(acc[0][j], h0, w2);                                  \
                fma2(acc[1][j], h1, w2);                                  \
                fma2(acc[2][j], h2, w2);                                  \
                accs[j] = fmaf(h6, w[j], accs[j]);                        \
            }                                                             \
        }

    // one activation iteration (unit-block i): 4 LDS + 5 MUFU + FMAs + STS
    #define ACT_I(i)                                                      \
        {                                                                 \
            int idx = lane + 32 * (i);                                    \
            if (idx < HID * RPW) {                                        \
                int u = idx / 7, rr = idx - u * 7;                        \
                float gi = gw[u * GW_STR + rr];                           \
                float gf = gw[(HID + u) * GW_STR + rr];                   \
                float gg = gw[(2 * HID + u) * GW_STR + rr];               \
                float go = gw[(3 * HID + u) * GW_STR + rr];               \
                float c = sig_a(gf) * creg[i] + sig_a(gi) * tanh_a(gg);   \
                creg[i] = c;                                              \
                hxw[(7 + u) * 8 + rr] = sig_a(go) * tanh_a(c);            \
            }                                                             \
        }

    // pre-loop: bias init + x-part for t=0
    #pragma unroll
    for (int j = 0; j < 7; ++j) {
        acc[0][j] = bdup[j]; acc[1][j] = bdup[j]; acc[2][j] = bdup[j];
        accs[j] = bflt[j];
    }
    #pragma unroll
    for (int k = 0; k < 7; ++k) GEMM_K7(k);

    for (int t = 0; t < NSTEP; ++t) {
        // prefetch x(t+1)
        int t2 = (t < NSTEP - 1) ? t + 1 : t;
        float xv0 = xp0[t2 * 13];
        float xv1 = i1ok ? xp1[t2 * 13] : 0.f;

        // h-part GEMM: k = 7..56
        #pragma unroll 5
        for (int k = 7; k < KDIM; ++k) GEMM_K7(k);

        // spill gates (float stores, stride 9 -> conflict-free)
        #pragma unroll
        for (int j = 0; j < 7; ++j) {
            int c = lane * 7 + j;
            if (c < GATE) {
                float* gp = gw + c * GW_STR;
                float2 v0 = unpk(acc[0][j]); gp[0] = v0.x; gp[1] = v0.y;
                float2 v1 = unpk(acc[1][j]); gp[2] = v1.x; gp[3] = v1.y;
                float2 v2 = unpk(acc[2][j]); gp[4] = v2.x; gp[5] = v2.y;
                gp[6] = accs[j];
            }
        }
        __syncwarp();   // gate stores & hx row reads done

        // stage x(t+1)
        hxw[xk0 * 8 + xr0] = xv0;
        if (i1ok) hxw[xk1 * 8 + xr1] = xv1;
        __syncwarp();

        // --- MANUALLY INTERLEAVED: x-part GEMM(t+1) [FMA pipe] woven with
        //     activation(t) [MUFU pipe]. x-part reads hx rows 0-6 only;
        //     activation writes rows 7-56 only -> independent. ---
        #pragma unroll
        for (int j = 0; j < 7; ++j) {
            acc[0][j] = bdup[j]; acc[1][j] = bdup[j]; acc[2][j] = bdup[j];
            accs[j] = bflt[j];
        }
        GEMM_K7(0); ACT_I(0);  ACT_I(1);
        GEMM_K7(1); ACT_I(2);
        GEMM_K7(2); ACT_I(3);  ACT_I(4);
        GEMM_K7(3); ACT_I(5);
        GEMM_K7(4); ACT_I(6);  ACT_I(7);
        GEMM_K7(5); ACT_I(8);
        GEMM_K7(6); ACT_I(9);  ACT_I(10);

        __syncwarp();   // h visible before next h-part GEMM
    }
    #undef GEMM_K7
    #undef ACT_I

    // ================== Phase A->B transition ==============================
    // Build warp-private X = [self6 | h] (rows 0..6, pad row 7) in the
    // disjoint Xw region; zero first.
    for (int i = lane; i < 448; i += 32) Xw[i] = 0.f;
    __syncwarp();
    // h rows from hxw (still intact)
    #pragma unroll
    for (int i = 0; i < 11; ++i) {
        int idx = lane + 32 * i;
        if (idx < HID * RPW) {
            int u = idx / 7, rr = idx - u * 7;
            Xw[(6 + u) * 8 + rr] = hxw[(7 + u) * 8 + rr];
        }
    }
    // self6: 42 values (7 rows x 6 dims), clamped rows
    {
        int idx0 = lane;                 // < 42 for all lanes 0..31
        int r0 = idx0 / 6, k0 = idx0 - r0 * 6;
        if (idx0 < 42)
            Xw[k0 * 8 + r0] = state[(size_t)min(b0 + r0, B_SIZE - 1) * ROWB + k0];
        int idx1 = lane + 32;
        int r1 = idx1 / 6, k1 = idx1 - r1 * 6;
        if (idx1 < 42)
            Xw[k1 * 8 + r1] = state[(size_t)min(b0 + r1, B_SIZE - 1) * ROWB + k1];
    }
    __syncthreads();    // everyone done with LSTM smem

    // stage MLP weights over the dead LSTM region
    float* w1s = sm + OFF_W1;
    float* b1s = sm + OFF_B1;
    float* w2s = sm + OFF_W2;
    float* b2s = sm + OFF_B2;
    float* w3s = sm + OFF_W3;
    float* b3s = sm + OFF_B3;
    float* w4s = sm + OFF_W4;
    float* b4s = sm + OFF_B4;
    for (int i = tid; i < 2100; i += THREADS)
        ((float4*)w1s)[i] = ((const float4*)w1)[i];
    for (int i = tid; i < 3750; i += THREADS)
        ((float4*)w2s)[i] = ((const float4*)w2)[i];
    for (int i = tid; i < 2500; i += THREADS)
        ((float4*)w3s)[i] = ((const float4*)w3)[i];
    if (tid < 150) b1s[tid] = b1[tid];
    if (tid < 100) { b2s[tid] = b2[tid]; b3s[tid] = b3[tid]; w4s[tid] = w4[tid]; }
    if (tid == 0) b4s[0] = b4[0];
    __syncthreads();    // weights visible

    // ======================= Phase B: MLP ==================================
    mlp_layer8<56, 150, 30, 5>(w1s, b1s, Xw, Yw, lane);
    mlp_layer8<150, 100, 25, 4>(w2s, b2s, Yw, Xw, lane);
    mlp_layer8<100, 100, 25, 4>(w3s, b3s, Xw, Yw, lane);

    // output: 8 rows (7 real), 4 lanes per row, shfl reduce
    {
        int r  = lane >> 2;          // 0..7
        int kk = lane & 3;           // 0..3
        float a = 0.f;
        #pragma unroll 5
        for (int k = kk; k < 100; k += 4)
            a = fmaf(Yw[k * 8 + r], w4s[k], a);
        a += __shfl_down_sync(0xFFFFFFFF, a, 2);
        a += __shfl_down_sync(0xFFFFFFFF, a, 1);
        if (kk == 0 && r < RPW && b0 + r < B_SIZE)
            out[b0 + r] = a + b4s[0];
    }
}

// ---------------------------------------------------------------------------
extern "C" void kernel_launch(void* const* d_in, const int* in_sizes, int n_in,
                              void* d_out, int out_size)
{
    (void)in_sizes; (void)n_in; (void)out_size;
    const float* state = (const float*)d_in[0];
    const float* wih   = (const float*)d_in[11];
    const float* whh   = (const float*)d_in[12];
    const float* bih   = (const float*)d_in[13];
    const float* bhh   = (const float*)d_in[14];
    const float* w1    = (const float*)d_in[15];
    const float* b1    = (const float*)d_in[16];
    const float* w2    = (const float*)d_in[17];
    const float* b2    = (const float*)d_in[18];
    const float* w3    = (const float*)d_in[19];
    const float* b3    = (const float*)d_in[20];
    const float* w4    = (const float*)d_in[21];
    const float* b4    = (const float*)d_in[22];
    float* out = (float*)d_out;

    cudaFuncSetAttribute(fused_kernel, cudaFuncAttributeMaxDynamicSharedMemorySize, SM_BYTES);

    fused_kernel<<<GRID, THREADS, SM_BYTES>>>(state, wih, whh, bih, bhh,
                                              w1, b1, w2, b2, w3, b3, w4, b4,
                                              out);
}